// round 3
// baseline (speedup 1.0000x reference)
#include <cuda_runtime.h>
#include <cuda_bf16.h>

#define N_NODES 50000
#define N_EDGES 800000
#define NODE_IN 256
#define EDGE_IN 64
#define HID 128
#define OUT_DIM 16
#define EPS 1e-5f

// Scratch (static device globals — no runtime allocation)
__device__ float g_hv[(size_t)N_NODES * HID];   // LN(GELU(node@Wn)) * exp(b_edge)
__device__ float g_h [(size_t)N_NODES * HID];   // segment-sum accumulator
__device__ uint4 g_WnF[16 * 16 * 32];           // pre-split W_node fragments (128 KB)
__device__ float g_P[HID], g_Q[HID];            // g_node*exp(b_edge), b_node*exp(b_edge)

__device__ __forceinline__ float gelu_exact(float x) {
    return 0.5f * x * (1.0f + erff(x * 0.7071067811865476f));
}

__device__ __forceinline__ void red_add_v2(float* p, float a, float b) {
    asm volatile("red.global.add.v2.f32 [%0], {%1,%2};"
                 :: "l"(p), "f"(a), "f"(b) : "memory");
}

__device__ __forceinline__ unsigned pack_bf2(float x, float y) {
    __nv_bfloat162 t = __floats2bfloat162_rn(x, y);
    return *reinterpret_cast<unsigned*>(&t);
}

// split a float2 into bf16-hi pair and bf16-lo (residual) pair, packed .b32
__device__ __forceinline__ void split2(float2 v, unsigned& hi, unsigned& lo) {
    float hx = __bfloat162float(__float2bfloat16_rn(v.x));
    float hy = __bfloat162float(__float2bfloat16_rn(v.y));
    hi = pack_bf2(hx, hy);
    lo = pack_bf2(v.x - hx, v.y - hy);
}

__device__ __forceinline__ void mma_bf16(float d[4],
                                         unsigned a0, unsigned a1, unsigned a2, unsigned a3,
                                         unsigned b0, unsigned b1) {
    asm volatile(
        "mma.sync.aligned.m16n8k16.row.col.f32.bf16.bf16.f32 "
        "{%0,%1,%2,%3}, {%4,%5,%6,%7}, {%8,%9}, {%0,%1,%2,%3};"
        : "+f"(d[0]), "+f"(d[1]), "+f"(d[2]), "+f"(d[3])
        : "r"(a0), "r"(a1), "r"(a2), "r"(a3), "r"(b0), "r"(b1));
}

// ---------------------------------------------------------------------------
// Kernel 0: prep — split W_node into mma B fragments; fold exp(b_edge) into
//           node LN affine params.
// ---------------------------------------------------------------------------
__global__ __launch_bounds__(256) void prep_kernel(
    const float* __restrict__ Wn, const float* __restrict__ gn,
    const float* __restrict__ bn, const float* __restrict__ be)
{
    const int i = blockIdx.x * 256 + threadIdx.x;   // 0..8191
    const int lane = i & 31, n = (i >> 5) & 15, ks = i >> 9;
    const int k0 = 16 * ks + 2 * (lane & 3);
    const int c  = 8 * n + (lane >> 2);
    const float v00 = Wn[(k0+0)*HID + c], v01 = Wn[(k0+1)*HID + c];
    const float v10 = Wn[(k0+8)*HID + c], v11 = Wn[(k0+9)*HID + c];
    unsigned h0, l0, h1, l1;
    split2(make_float2(v00, v01), h0, l0);
    split2(make_float2(v10, v11), h1, l1);
    g_WnF[i] = make_uint4(h0, h1, l0, l1);
    if (i < HID) {
        const float e = __expf(be[i]);
        g_P[i] = gn[i] * e;
        g_Q[i] = bn[i] * e;
    }
}

// ---------------------------------------------------------------------------
// Kernel 1: hv = (LN(GELU(nf @ Wn)) scaled by exp(b_edge)), MMA split-3.
//           Also zeroes this tile's 16 rows of g_h.
// One warp = 16 nodes; B fragments streamed from g_WnF (L1-resident).
// ---------------------------------------------------------------------------
__global__ __launch_bounds__(128) void node_proj_kernel(const float* __restrict__ nf)
{
    const int tid = threadIdx.x;
    const int w = tid >> 5, lane = tid & 31;
    const int gid = lane >> 2, tig = lane & 3;
    const int nwarp = gridDim.x * 4;
    const float2* nf2 = (const float2*)nf;

    for (int t = blockIdx.x * 4 + w; t < N_NODES / 16; t += nwarp) {
        const int n0 = t * 16;

        // zero accumulator rows n0..n0+15 (8 KB per warp)
        {
            float4* hz = (float4*)(g_h + (size_t)n0 * HID);
            const float4 z4 = make_float4(0.f, 0.f, 0.f, 0.f);
            #pragma unroll
            for (int i = 0; i < 16; i++) hz[i * 32 + lane] = z4;
        }

        float d[16][4];
        #pragma unroll
        for (int n = 0; n < 16; n++) { d[n][0]=0.f; d[n][1]=0.f; d[n][2]=0.f; d[n][3]=0.f; }

        const size_t r0 = (size_t)(n0 + gid) * (NODE_IN/2);
        const size_t r1 = (size_t)(n0 + gid + 8) * (NODE_IN/2);
        #pragma unroll 4
        for (int ks = 0; ks < 16; ks++) {
            const float2 f0 = nf2[r0 + 8*ks + tig    ];
            const float2 f1 = nf2[r1 + 8*ks + tig    ];
            const float2 f2 = nf2[r0 + 8*ks + tig + 4];
            const float2 f3 = nf2[r1 + 8*ks + tig + 4];
            unsigned ah0, al0, ah1, al1, ah2, al2, ah3, al3;
            split2(f0, ah0, al0); split2(f1, ah1, al1);
            split2(f2, ah2, al2); split2(f3, ah3, al3);

            const uint4* Bk = &g_WnF[ks * 512 + lane];
            #pragma unroll
            for (int n = 0; n < 16; n++) {
                const uint4 bb = __ldg(&Bk[n * 32]);
                mma_bf16(d[n], ah0, ah1, ah2, ah3, bb.x, bb.y);
                mma_bf16(d[n], ah0, ah1, ah2, ah3, bb.z, bb.w);
                mma_bf16(d[n], al0, al1, al2, al3, bb.x, bb.y);
            }
        }

        // GELU
        #pragma unroll
        for (int n = 0; n < 16; n++) {
            d[n][0] = gelu_exact(d[n][0]); d[n][1] = gelu_exact(d[n][1]);
            d[n][2] = gelu_exact(d[n][2]); d[n][3] = gelu_exact(d[n][3]);
        }

        // LN stats per node row (quad reduce)
        float s0 = 0.f, q0 = 0.f, s1 = 0.f, q1 = 0.f;
        #pragma unroll
        for (int n = 0; n < 16; n++) {
            s0 += d[n][0] + d[n][1];
            q0 += d[n][0]*d[n][0] + d[n][1]*d[n][1];
            s1 += d[n][2] + d[n][3];
            q1 += d[n][2]*d[n][2] + d[n][3]*d[n][3];
        }
        s0 += __shfl_xor_sync(0xffffffffu, s0, 1); s0 += __shfl_xor_sync(0xffffffffu, s0, 2);
        q0 += __shfl_xor_sync(0xffffffffu, q0, 1); q0 += __shfl_xor_sync(0xffffffffu, q0, 2);
        s1 += __shfl_xor_sync(0xffffffffu, s1, 1); s1 += __shfl_xor_sync(0xffffffffu, s1, 2);
        q1 += __shfl_xor_sync(0xffffffffu, q1, 1); q1 += __shfl_xor_sync(0xffffffffu, q1, 2);
        const float mu0   = s0 * (1.f / HID);
        const float rstd0 = rsqrtf(q0 * (1.f / HID) - mu0*mu0 + EPS);
        const float mu1   = s1 * (1.f / HID);
        const float rstd1 = rsqrtf(q1 * (1.f / HID) - mu1*mu1 + EPS);

        float* o0 = g_hv + (size_t)(n0 + gid    ) * HID;
        float* o1 = g_hv + (size_t)(n0 + gid + 8) * HID;
        #pragma unroll
        for (int n = 0; n < 16; n++) {
            const int c0 = 8*n + 2*tig;
            const float2 P2 = *(const float2*)(g_P + c0);
            const float2 Q2 = *(const float2*)(g_Q + c0);
            *(float2*)(o0 + c0) = make_float2(
                (d[n][0]-mu0)*rstd0*P2.x + Q2.x, (d[n][1]-mu0)*rstd0*P2.y + Q2.y);
            *(float2*)(o1 + c0) = make_float2(
                (d[n][2]-mu1)*rstd1*P2.x + Q2.x, (d[n][3]-mu1)*rstd1*P2.y + Q2.y);
        }
    }
}

// ---------------------------------------------------------------------------
// Edge epilogue for one m16 accumulator set.
// ---------------------------------------------------------------------------
__device__ __forceinline__ void edge_epi(
    const float (&d)[16][4], int ebase, int gid, int tig,
    const float* __restrict__ g, const int* __restrict__ src,
    const int* __restrict__ dst)
{
    float s0 = 0.f, q0 = 0.f, s1 = 0.f, q1 = 0.f;
    #pragma unroll
    for (int n = 0; n < 16; n++) {
        s0 += d[n][0] + d[n][1];
        q0 += d[n][0]*d[n][0] + d[n][1]*d[n][1];
        s1 += d[n][2] + d[n][3];
        q1 += d[n][2]*d[n][2] + d[n][3]*d[n][3];
    }
    s0 += __shfl_xor_sync(0xffffffffu, s0, 1); s0 += __shfl_xor_sync(0xffffffffu, s0, 2);
    q0 += __shfl_xor_sync(0xffffffffu, q0, 1); q0 += __shfl_xor_sync(0xffffffffu, q0, 2);
    s1 += __shfl_xor_sync(0xffffffffu, s1, 1); s1 += __shfl_xor_sync(0xffffffffu, s1, 2);
    q1 += __shfl_xor_sync(0xffffffffu, q1, 1); q1 += __shfl_xor_sync(0xffffffffu, q1, 2);

    const float mu0   = s0 * (1.f / HID);
    const float rstd0 = rsqrtf(q0 * (1.f / HID) - mu0*mu0 + EPS);
    const float mu1   = s1 * (1.f / HID);
    const float rstd1 = rsqrtf(q1 * (1.f / HID) - mu1*mu1 + EPS);

    const int er0 = ebase + gid, er1 = ebase + gid + 8;
    const int sv0 = src[er0], dv0 = dst[er0];
    const int sv1 = src[er1], dv1 = dst[er1];
    const float2* hv0 = (const float2*)g_hv + (size_t)sv0 * 64 + tig;
    const float2* hv1 = (const float2*)g_hv + (size_t)sv1 * 64 + tig;
    float* o0 = g_h + (size_t)dv0 * HID + 2*tig;
    float* o1 = g_h + (size_t)dv1 * HID + 2*tig;

    #pragma unroll
    for (int n = 0; n < 16; n++) {
        const float2 ge = *(const float2*)(g + 8*n + 2*tig);
        const float e00 = __expf((d[n][0] - mu0) * rstd0 * ge.x);
        const float e01 = __expf((d[n][1] - mu0) * rstd0 * ge.y);
        const float e10 = __expf((d[n][2] - mu1) * rstd1 * ge.x);
        const float e11 = __expf((d[n][3] - mu1) * rstd1 * ge.y);
        const float2 h0 = hv0[4*n];
        const float2 h1 = hv1[4*n];
        red_add_v2(o0 + 8*n, h0.x * e00, h0.y * e01);
        red_add_v2(o1 + 8*n, h1.x * e10, h1.y * e11);
    }
}

// ---------------------------------------------------------------------------
// Kernel 2 (hot): per 32-edge warp tile (two m16 tiles sharing B reads):
//   z = ef @ W_edge (mma bf16 split-3); he = exp(LN(z)*g); red.add(h[dst], hv[src]*he)
// ---------------------------------------------------------------------------
__global__ __launch_bounds__(128, 2) void edge_kernel(
    const float* __restrict__ ef, const int* __restrict__ src,
    const int* __restrict__ dst,  const float* __restrict__ We,
    const float* __restrict__ g)
{
    // Pre-split B fragments: [ks][n][lane] -> {bhi0, bhi1, blo0, blo1}
    __shared__ uint4 sB[4 * 16 * 32];   // 32 KB

    const int tid = threadIdx.x;
    for (int i = tid; i < 2048; i += 128) {
        const int lane = i & 31, n = (i >> 5) & 15, ks = i >> 9;
        const int k0 = 16*ks + 2*(lane & 3);
        const int c  = 8*n + (lane >> 2);
        const float v00 = We[(k0+0)*HID + c], v01 = We[(k0+1)*HID + c];
        const float v10 = We[(k0+8)*HID + c], v11 = We[(k0+9)*HID + c];
        unsigned h0, l0, h1, l1;
        split2(make_float2(v00, v01), h0, l0);
        split2(make_float2(v10, v11), h1, l1);
        sB[i] = make_uint4(h0, h1, l0, l1);
    }
    __syncthreads();

    const int w = tid >> 5, lane = tid & 31;
    const int gid = lane >> 2, tig = lane & 3;
    const float2* ef2 = (const float2*)ef;
    const int nTiles = N_EDGES / 32;      // 25000, exact
    const int nwarp  = gridDim.x * 4;

    for (int t = blockIdx.x * 4 + w; t < nTiles; t += nwarp) {
        const int e0 = t * 32;

        float d0[16][4], d1[16][4];
        #pragma unroll
        for (int n = 0; n < 16; n++) {
            d0[n][0]=0.f; d0[n][1]=0.f; d0[n][2]=0.f; d0[n][3]=0.f;
            d1[n][0]=0.f; d1[n][1]=0.f; d1[n][2]=0.f; d1[n][3]=0.f;
        }

        const size_t ra0 = (size_t)(e0 + gid     ) * 32;
        const size_t ra1 = (size_t)(e0 + gid +  8) * 32;
        const size_t rb0 = (size_t)(e0 + gid + 16) * 32;
        const size_t rb1 = (size_t)(e0 + gid + 24) * 32;
        #pragma unroll
        for (int ks = 0; ks < 4; ks++) {
            unsigned xh0,xl0,xh1,xl1,xh2,xl2,xh3,xl3;   // tile0 A
            unsigned yh0,yl0,yh1,yl1,yh2,yl2,yh3,yl3;   // tile1 A
            split2(ef2[ra0 + 8*ks + tig    ], xh0, xl0);
            split2(ef2[ra1 + 8*ks + tig    ], xh1, xl1);
            split2(ef2[ra0 + 8*ks + tig + 4], xh2, xl2);
            split2(ef2[ra1 + 8*ks + tig + 4], xh3, xl3);
            split2(ef2[rb0 + 8*ks + tig    ], yh0, yl0);
            split2(ef2[rb1 + 8*ks + tig    ], yh1, yl1);
            split2(ef2[rb0 + 8*ks + tig + 4], yh2, yl2);
            split2(ef2[rb1 + 8*ks + tig + 4], yh3, yl3);

            const uint4* sBk = &sB[ks * 512 + lane];
            #pragma unroll
            for (int n = 0; n < 16; n++) {
                const uint4 bb = sBk[n * 32];
                mma_bf16(d0[n], xh0, xh1, xh2, xh3, bb.x, bb.y);
                mma_bf16(d0[n], xh0, xh1, xh2, xh3, bb.z, bb.w);
                mma_bf16(d0[n], xl0, xl1, xl2, xl3, bb.x, bb.y);
                mma_bf16(d1[n], yh0, yh1, yh2, yh3, bb.x, bb.y);
                mma_bf16(d1[n], yh0, yh1, yh2, yh3, bb.z, bb.w);
                mma_bf16(d1[n], yl0, yl1, yl2, yl3, bb.x, bb.y);
            }
        }

        edge_epi(d0, e0,      gid, tig, g, src, dst);
        edge_epi(d1, e0 + 16, gid, tig, g, src, dst);
    }
}

// ---------------------------------------------------------------------------
// Kernel 3: out = LayerNorm(GELU(h @ W_out))
// ---------------------------------------------------------------------------
__global__ __launch_bounds__(256) void out_kernel(
    const float* __restrict__ Wo, const float* __restrict__ g,
    const float* __restrict__ b,  float* __restrict__ out)
{
    __shared__ float sH [16 * HID];        // 8 KB
    __shared__ float sWo[HID * OUT_DIM];   // 8 KB

    const int tid = threadIdx.x;
    const int n0  = blockIdx.x * 16;
    {
        const float4* hv4 = (const float4*)(g_h + (size_t)n0 * HID);
        float4* sH4 = (float4*)sH;
        #pragma unroll
        for (int i = tid; i < 512; i += 256) sH4[i] = hv4[i];
        const float4* wv4 = (const float4*)Wo;
        float4* sW4 = (float4*)sWo;
        #pragma unroll
        for (int i = tid; i < 512; i += 256) sW4[i] = wv4[i];
    }
    __syncthreads();

    const int n = tid >> 4, c = tid & 15;
    float acc = 0.f;
    const float4* sHn = (const float4*)(sH + n * HID);
    #pragma unroll 4
    for (int k4 = 0; k4 < HID / 4; k4++) {
        const float4 a = sHn[k4];
        acc += a.x * sWo[(4*k4+0)*OUT_DIM + c];
        acc += a.y * sWo[(4*k4+1)*OUT_DIM + c];
        acc += a.z * sWo[(4*k4+2)*OUT_DIM + c];
        acc += a.w * sWo[(4*k4+3)*OUT_DIM + c];
    }

    const float v = gelu_exact(acc);
    float s = v, s2 = v * v;
    #pragma unroll
    for (int off = 8; off; off >>= 1) {
        s  += __shfl_xor_sync(0xffffffffu, s,  off);
        s2 += __shfl_xor_sync(0xffffffffu, s2, off);
    }
    const float mu   = s * (1.f / OUT_DIM);
    const float rstd = rsqrtf(s2 * (1.f / OUT_DIM) - mu * mu + EPS);
    out[(size_t)(n0 + n) * OUT_DIM + c] = (v - mu) * rstd * g[c] + b[c];
}

// ---------------------------------------------------------------------------
extern "C" void kernel_launch(void* const* d_in, const int* in_sizes, int n_in,
                              void* d_out, int out_size) {
    const float* node_feats = (const float*)d_in[0];
    const float* edge_feats = (const float*)d_in[1];
    const int*   src        = (const int*)  d_in[2];
    const int*   dst        = (const int*)  d_in[3];
    const float* W_node     = (const float*)d_in[4];
    const float* g_node     = (const float*)d_in[5];
    const float* b_node     = (const float*)d_in[6];
    const float* W_edge     = (const float*)d_in[7];
    const float* g_edge     = (const float*)d_in[8];
    const float* b_edge     = (const float*)d_in[9];
    const float* W_out      = (const float*)d_in[10];
    const float* g_out      = (const float*)d_in[11];
    const float* b_out      = (const float*)d_in[12];
    float* out = (float*)d_out;

    prep_kernel<<<32, 256>>>(W_node, g_node, b_node, b_edge);
    node_proj_kernel<<<444, 128>>>(node_feats);
    edge_kernel<<<296, 128>>>(edge_feats, src, dst, W_edge, g_edge);
    out_kernel<<<N_NODES / 16, 256>>>(W_out, g_out, b_out, out);
}

// round 4
// speedup vs baseline: 1.2547x; 1.2547x over previous
#include <cuda_runtime.h>
#include <cuda_bf16.h>

#define N_NODES 50000
#define N_EDGES 800000
#define NODE_IN 256
#define EDGE_IN 64
#define HID 128
#define OUT_DIM 16
#define EPS 1e-5f

// Scratch (static device globals — no runtime allocation)
__device__ float g_hv[(size_t)N_NODES * HID];   // LN(GELU(node@Wn)) * exp(b_edge)
__device__ float g_h [(size_t)N_NODES * HID];   // segment-sum accumulator
__device__ uint4 g_WnF[16 * 16 * 32];           // pre-split W_node fragments (128 KB)
__device__ float g_P[HID], g_Q[HID];            // g_node*exp(b_edge), b_node*exp(b_edge)

__device__ __forceinline__ float gelu_exact(float x) {
    return 0.5f * x * (1.0f + erff(x * 0.7071067811865476f));
}

__device__ __forceinline__ void red_add_v2(float* p, float a, float b) {
    asm volatile("red.global.add.v2.f32 [%0], {%1,%2};"
                 :: "l"(p), "f"(a), "f"(b) : "memory");
}

__device__ __forceinline__ unsigned pack_bf2(float x, float y) {
    __nv_bfloat162 t = __floats2bfloat162_rn(x, y);
    return *reinterpret_cast<unsigned*>(&t);
}

// split a float2 into bf16-hi pair and bf16-lo (residual) pair, packed .b32
__device__ __forceinline__ void split2(float2 v, unsigned& hi, unsigned& lo) {
    float hx = __bfloat162float(__float2bfloat16_rn(v.x));
    float hy = __bfloat162float(__float2bfloat16_rn(v.y));
    hi = pack_bf2(hx, hy);
    lo = pack_bf2(v.x - hx, v.y - hy);
}

__device__ __forceinline__ void mma_bf16(float d[4],
                                         unsigned a0, unsigned a1, unsigned a2, unsigned a3,
                                         unsigned b0, unsigned b1) {
    asm volatile(
        "mma.sync.aligned.m16n8k16.row.col.f32.bf16.bf16.f32 "
        "{%0,%1,%2,%3}, {%4,%5,%6,%7}, {%8,%9}, {%0,%1,%2,%3};"
        : "+f"(d[0]), "+f"(d[1]), "+f"(d[2]), "+f"(d[3])
        : "r"(a0), "r"(a1), "r"(a2), "r"(a3), "r"(b0), "r"(b1));
}

// ---------------------------------------------------------------------------
// Kernel 0: prep — split W_node into mma B fragments; fold exp(b_edge) into
//           node LN affine params.
// ---------------------------------------------------------------------------
__global__ __launch_bounds__(256) void prep_kernel(
    const float* __restrict__ Wn, const float* __restrict__ gn,
    const float* __restrict__ bn, const float* __restrict__ be)
{
    const int i = blockIdx.x * 256 + threadIdx.x;   // 0..8191
    const int lane = i & 31, n = (i >> 5) & 15, ks = i >> 9;
    const int k0 = 16 * ks + 2 * (lane & 3);
    const int c  = 8 * n + (lane >> 2);
    const float v00 = Wn[(k0+0)*HID + c], v01 = Wn[(k0+1)*HID + c];
    const float v10 = Wn[(k0+8)*HID + c], v11 = Wn[(k0+9)*HID + c];
    unsigned h0, l0, h1, l1;
    split2(make_float2(v00, v01), h0, l0);
    split2(make_float2(v10, v11), h1, l1);
    g_WnF[i] = make_uint4(h0, h1, l0, l1);
    if (i < HID) {
        const float e = __expf(be[i]);
        g_P[i] = gn[i] * e;
        g_Q[i] = bn[i] * e;
    }
}

// ---------------------------------------------------------------------------
// Kernel 1: hv = (LN(GELU(nf @ Wn)) scaled by exp(b_edge)), MMA split-3.
// Full W_node fragment table (128 KB) in dynamic smem; 12 warps/SM,
// warps grid-stride over 16-node tiles. Also zeroes each tile's g_h rows.
// ---------------------------------------------------------------------------
__global__ __launch_bounds__(384) void node_proj_kernel(const float* __restrict__ nf)
{
    extern __shared__ uint4 sBn[];   // 16*16*32 = 8192 uint4 = 128 KB

    const int tid = threadIdx.x;
    for (int i = tid; i < 8192; i += 384) sBn[i] = g_WnF[i];
    __syncthreads();

    const int w = tid >> 5, lane = tid & 31;
    const int gid = lane >> 2, tig = lane & 3;
    const int nwarp = gridDim.x * 12;
    const float2* nf2 = (const float2*)nf;

    for (int t = blockIdx.x * 12 + w; t < N_NODES / 16; t += nwarp) {
        const int n0 = t * 16;

        // zero accumulator rows n0..n0+15 (8 KB per warp)
        {
            float4* hz = (float4*)(g_h + (size_t)n0 * HID);
            const float4 z4 = make_float4(0.f, 0.f, 0.f, 0.f);
            #pragma unroll
            for (int i = 0; i < 16; i++) hz[i * 32 + lane] = z4;
        }

        float d[16][4];
        #pragma unroll
        for (int n = 0; n < 16; n++) { d[n][0]=0.f; d[n][1]=0.f; d[n][2]=0.f; d[n][3]=0.f; }

        const size_t r0 = (size_t)(n0 + gid) * (NODE_IN/2);
        const size_t r1 = (size_t)(n0 + gid + 8) * (NODE_IN/2);
        #pragma unroll 4
        for (int ks = 0; ks < 16; ks++) {
            const float2 f0 = nf2[r0 + 8*ks + tig    ];
            const float2 f1 = nf2[r1 + 8*ks + tig    ];
            const float2 f2 = nf2[r0 + 8*ks + tig + 4];
            const float2 f3 = nf2[r1 + 8*ks + tig + 4];
            unsigned ah0, al0, ah1, al1, ah2, al2, ah3, al3;
            split2(f0, ah0, al0); split2(f1, ah1, al1);
            split2(f2, ah2, al2); split2(f3, ah3, al3);

            const uint4* Bk = &sBn[ks * 512 + lane];
            #pragma unroll
            for (int n = 0; n < 16; n++) {
                const uint4 bb = Bk[n * 32];
                mma_bf16(d[n], ah0, ah1, ah2, ah3, bb.x, bb.y);
                mma_bf16(d[n], ah0, ah1, ah2, ah3, bb.z, bb.w);
                mma_bf16(d[n], al0, al1, al2, al3, bb.x, bb.y);
            }
        }

        // GELU
        #pragma unroll
        for (int n = 0; n < 16; n++) {
            d[n][0] = gelu_exact(d[n][0]); d[n][1] = gelu_exact(d[n][1]);
            d[n][2] = gelu_exact(d[n][2]); d[n][3] = gelu_exact(d[n][3]);
        }

        // LN stats per node row (quad reduce)
        float s0 = 0.f, q0 = 0.f, s1 = 0.f, q1 = 0.f;
        #pragma unroll
        for (int n = 0; n < 16; n++) {
            s0 += d[n][0] + d[n][1];
            q0 += d[n][0]*d[n][0] + d[n][1]*d[n][1];
            s1 += d[n][2] + d[n][3];
            q1 += d[n][2]*d[n][2] + d[n][3]*d[n][3];
        }
        s0 += __shfl_xor_sync(0xffffffffu, s0, 1); s0 += __shfl_xor_sync(0xffffffffu, s0, 2);
        q0 += __shfl_xor_sync(0xffffffffu, q0, 1); q0 += __shfl_xor_sync(0xffffffffu, q0, 2);
        s1 += __shfl_xor_sync(0xffffffffu, s1, 1); s1 += __shfl_xor_sync(0xffffffffu, s1, 2);
        q1 += __shfl_xor_sync(0xffffffffu, q1, 1); q1 += __shfl_xor_sync(0xffffffffu, q1, 2);
        const float mu0   = s0 * (1.f / HID);
        const float rstd0 = rsqrtf(q0 * (1.f / HID) - mu0*mu0 + EPS);
        const float mu1   = s1 * (1.f / HID);
        const float rstd1 = rsqrtf(q1 * (1.f / HID) - mu1*mu1 + EPS);

        float* o0 = g_hv + (size_t)(n0 + gid    ) * HID;
        float* o1 = g_hv + (size_t)(n0 + gid + 8) * HID;
        #pragma unroll
        for (int n = 0; n < 16; n++) {
            const int c0 = 8*n + 2*tig;
            const float2 P2 = *(const float2*)(g_P + c0);
            const float2 Q2 = *(const float2*)(g_Q + c0);
            *(float2*)(o0 + c0) = make_float2(
                (d[n][0]-mu0)*rstd0*P2.x + Q2.x, (d[n][1]-mu0)*rstd0*P2.y + Q2.y);
            *(float2*)(o1 + c0) = make_float2(
                (d[n][2]-mu1)*rstd1*P2.x + Q2.x, (d[n][3]-mu1)*rstd1*P2.y + Q2.y);
        }
    }
}

// ---------------------------------------------------------------------------
// Kernel 2 (hot): per 16-edge warp tile:  (exact R2 version — measured good)
//   z = ef @ W_edge via mma.sync bf16 3-term split (~fp32 accuracy)
//   he = exp(LN(z)*g)  (b folded into hv);  red.add(h[dst], hv[src]*he)
// ---------------------------------------------------------------------------
__global__ __launch_bounds__(128, 3) void edge_kernel(
    const float* __restrict__ ef, const int* __restrict__ src,
    const int* __restrict__ dst,  const float* __restrict__ We,
    const float* __restrict__ g)
{
    // Pre-split B fragments: [ks][n][lane] -> {bhi0, bhi1, blo0, blo1}
    __shared__ uint4 sB[4 * 16 * 32];   // 32 KB

    const int tid = threadIdx.x;
    for (int i = tid; i < 2048; i += 128) {
        const int lane = i & 31, n = (i >> 5) & 15, ks = i >> 9;
        const int k0 = 16*ks + 2*(lane & 3);
        const int c  = 8*n + (lane >> 2);
        const float v00 = We[(k0+0)*HID + c], v01 = We[(k0+1)*HID + c];
        const float v10 = We[(k0+8)*HID + c], v11 = We[(k0+9)*HID + c];
        unsigned h0, l0, h1, l1;
        split2(make_float2(v00, v01), h0, l0);
        split2(make_float2(v10, v11), h1, l1);
        sB[i] = make_uint4(h0, h1, l0, l1);
    }
    __syncthreads();

    const int w = tid >> 5, lane = tid & 31;
    const int gid = lane >> 2, tig = lane & 3;

    // per-lane gamma pairs for cols 8n + 2*tig + {0,1}
    float2 ge[16];
    #pragma unroll
    for (int n = 0; n < 16; n++) ge[n] = *(const float2*)(g + 8*n + 2*tig);

    const float2* ef2 = (const float2*)ef;
    const int nTiles = N_EDGES / 16;      // 50000, exact
    const int nwarp  = gridDim.x * 4;

    for (int t = blockIdx.x * 4 + w; t < nTiles; t += nwarp) {
        const int e0 = t * 16;

        float d[16][4];
        #pragma unroll
        for (int n = 0; n < 16; n++) { d[n][0]=0.f; d[n][1]=0.f; d[n][2]=0.f; d[n][3]=0.f; }

        #pragma unroll
        for (int ks = 0; ks < 4; ks++) {
            const float2 f0 = ef2[(size_t)(e0 + gid    ) * 32 + 8*ks + tig    ];
            const float2 f1 = ef2[(size_t)(e0 + gid + 8) * 32 + 8*ks + tig    ];
            const float2 f2 = ef2[(size_t)(e0 + gid    ) * 32 + 8*ks + tig + 4];
            const float2 f3 = ef2[(size_t)(e0 + gid + 8) * 32 + 8*ks + tig + 4];
            unsigned ah0, al0, ah1, al1, ah2, al2, ah3, al3;
            split2(f0, ah0, al0); split2(f1, ah1, al1);
            split2(f2, ah2, al2); split2(f3, ah3, al3);

            const uint4* sBk = &sB[ks * 512 + lane];
            #pragma unroll
            for (int n = 0; n < 16; n++) {
                const uint4 bb = sBk[n * 32];
                mma_bf16(d[n], ah0, ah1, ah2, ah3, bb.x, bb.y);  // hi*hi
                mma_bf16(d[n], ah0, ah1, ah2, ah3, bb.z, bb.w);  // hi*lo
                mma_bf16(d[n], al0, al1, al2, al3, bb.x, bb.y);  // lo*hi
            }
        }

        // LN stats per edge row (quad-reduce: lanes sharing gid)
        float s0 = 0.f, q0 = 0.f, s1 = 0.f, q1 = 0.f;
        #pragma unroll
        for (int n = 0; n < 16; n++) {
            s0 += d[n][0] + d[n][1];
            q0 += d[n][0]*d[n][0] + d[n][1]*d[n][1];
            s1 += d[n][2] + d[n][3];
            q1 += d[n][2]*d[n][2] + d[n][3]*d[n][3];
        }
        s0 += __shfl_xor_sync(0xffffffffu, s0, 1); s0 += __shfl_xor_sync(0xffffffffu, s0, 2);
        q0 += __shfl_xor_sync(0xffffffffu, q0, 1); q0 += __shfl_xor_sync(0xffffffffu, q0, 2);
        s1 += __shfl_xor_sync(0xffffffffu, s1, 1); s1 += __shfl_xor_sync(0xffffffffu, s1, 2);
        q1 += __shfl_xor_sync(0xffffffffu, q1, 1); q1 += __shfl_xor_sync(0xffffffffu, q1, 2);

        const float mu0   = s0 * (1.f / HID);
        const float rstd0 = rsqrtf(q0 * (1.f / HID) - mu0*mu0 + EPS);
        const float mu1   = s1 * (1.f / HID);
        const float rstd1 = rsqrtf(q1 * (1.f / HID) - mu1*mu1 + EPS);

        const int er0 = e0 + gid, er1 = e0 + gid + 8;
        const int sv0 = src[er0], dv0 = dst[er0];
        const int sv1 = src[er1], dv1 = dst[er1];
        const float2* hv0 = (const float2*)g_hv + (size_t)sv0 * 64 + tig;
        const float2* hv1 = (const float2*)g_hv + (size_t)sv1 * 64 + tig;
        float* o0 = g_h + (size_t)dv0 * HID + 2*tig;
        float* o1 = g_h + (size_t)dv1 * HID + 2*tig;

        #pragma unroll
        for (int n = 0; n < 16; n++) {
            const float e00 = __expf((d[n][0] - mu0) * rstd0 * ge[n].x);
            const float e01 = __expf((d[n][1] - mu0) * rstd0 * ge[n].y);
            const float e10 = __expf((d[n][2] - mu1) * rstd1 * ge[n].x);
            const float e11 = __expf((d[n][3] - mu1) * rstd1 * ge[n].y);
            const float2 h0 = hv0[4*n];
            const float2 h1 = hv1[4*n];
            red_add_v2(o0 + 8*n, h0.x * e00, h0.y * e01);
            red_add_v2(o1 + 8*n, h1.x * e10, h1.y * e11);
        }
    }
}

// ---------------------------------------------------------------------------
// Kernel 3: out = LayerNorm(GELU(h @ W_out))
// ---------------------------------------------------------------------------
__global__ __launch_bounds__(256) void out_kernel(
    const float* __restrict__ Wo, const float* __restrict__ g,
    const float* __restrict__ b,  float* __restrict__ out)
{
    __shared__ float sH [16 * HID];        // 8 KB
    __shared__ float sWo[HID * OUT_DIM];   // 8 KB

    const int tid = threadIdx.x;
    const int n0  = blockIdx.x * 16;
    {
        const float4* hv4 = (const float4*)(g_h + (size_t)n0 * HID);
        float4* sH4 = (float4*)sH;
        #pragma unroll
        for (int i = tid; i < 512; i += 256) sH4[i] = hv4[i];
        const float4* wv4 = (const float4*)Wo;
        float4* sW4 = (float4*)sWo;
        #pragma unroll
        for (int i = tid; i < 512; i += 256) sW4[i] = wv4[i];
    }
    __syncthreads();

    const int n = tid >> 4, c = tid & 15;
    float acc = 0.f;
    const float4* sHn = (const float4*)(sH + n * HID);
    #pragma unroll 4
    for (int k4 = 0; k4 < HID / 4; k4++) {
        const float4 a = sHn[k4];
        acc += a.x * sWo[(4*k4+0)*OUT_DIM + c];
        acc += a.y * sWo[(4*k4+1)*OUT_DIM + c];
        acc += a.z * sWo[(4*k4+2)*OUT_DIM + c];
        acc += a.w * sWo[(4*k4+3)*OUT_DIM + c];
    }

    const float v = gelu_exact(acc);
    float s = v, s2 = v * v;
    #pragma unroll
    for (int off = 8; off; off >>= 1) {
        s  += __shfl_xor_sync(0xffffffffu, s,  off);
        s2 += __shfl_xor_sync(0xffffffffu, s2, off);
    }
    const float mu   = s * (1.f / OUT_DIM);
    const float rstd = rsqrtf(s2 * (1.f / OUT_DIM) - mu * mu + EPS);
    out[(size_t)(n0 + n) * OUT_DIM + c] = (v - mu) * rstd * g[c] + b[c];
}

// ---------------------------------------------------------------------------
extern "C" void kernel_launch(void* const* d_in, const int* in_sizes, int n_in,
                              void* d_out, int out_size) {
    const float* node_feats = (const float*)d_in[0];
    const float* edge_feats = (const float*)d_in[1];
    const int*   src        = (const int*)  d_in[2];
    const int*   dst        = (const int*)  d_in[3];
    const float* W_node     = (const float*)d_in[4];
    const float* g_node     = (const float*)d_in[5];
    const float* b_node     = (const float*)d_in[6];
    const float* W_edge     = (const float*)d_in[7];
    const float* g_edge     = (const float*)d_in[8];
    const float* b_edge     = (const float*)d_in[9];
    const float* W_out      = (const float*)d_in[10];
    const float* g_out      = (const float*)d_in[11];
    const float* b_out      = (const float*)d_in[12];
    float* out = (float*)d_out;

    static bool attr_set = false;
    if (!attr_set) {
        cudaFuncSetAttribute(node_proj_kernel,
                             cudaFuncAttributeMaxDynamicSharedMemorySize, 131072);
        attr_set = true;
    }

    prep_kernel<<<32, 256>>>(W_node, g_node, b_node, b_edge);
    node_proj_kernel<<<148, 384, 131072>>>(node_feats);
    edge_kernel<<<444, 128>>>(edge_feats, src, dst, W_edge, g_edge);
    out_kernel<<<N_NODES / 16, 256>>>(W_out, g_out, b_out, out);
}

// round 5
// speedup vs baseline: 1.3347x; 1.0637x over previous
#include <cuda_runtime.h>
#include <cuda_bf16.h>

#define N_NODES 50000
#define N_EDGES 800000
#define NODE_IN 256
#define EDGE_IN 64
#define HID 128
#define OUT_DIM 16
#define EPS 1e-5f

// Scratch (static device globals — no runtime allocation)
__device__ float g_hv[(size_t)N_NODES * HID];   // LN(GELU(node@Wn)) * exp(b_edge)
__device__ float g_h [(size_t)N_NODES * HID];   // segment-sum accumulator
__device__ uint4 g_WnF[16 * 16 * 32];           // pre-split W_node fragments (128 KB)
__device__ float g_P[HID], g_Q[HID];            // g_node*exp(b_edge), b_node*exp(b_edge)

__device__ __forceinline__ float gelu_exact(float x) {
    return 0.5f * x * (1.0f + erff(x * 0.7071067811865476f));
}

__device__ __forceinline__ void red_add_v4(float* p, float a, float b, float c, float d) {
    asm volatile("red.global.add.v4.f32 [%0], {%1,%2,%3,%4};"
                 :: "l"(p), "f"(a), "f"(b), "f"(c), "f"(d) : "memory");
}

__device__ __forceinline__ unsigned pack_bf2(float x, float y) {
    __nv_bfloat162 t = __floats2bfloat162_rn(x, y);
    return *reinterpret_cast<unsigned*>(&t);
}

// split a float2 into bf16-hi pair and bf16-lo (residual) pair, packed .b32
__device__ __forceinline__ void split2(float2 v, unsigned& hi, unsigned& lo) {
    float hx = __bfloat162float(__float2bfloat16_rn(v.x));
    float hy = __bfloat162float(__float2bfloat16_rn(v.y));
    hi = pack_bf2(hx, hy);
    lo = pack_bf2(v.x - hx, v.y - hy);
}

__device__ __forceinline__ void mma_bf16(float d[4],
                                         unsigned a0, unsigned a1, unsigned a2, unsigned a3,
                                         unsigned b0, unsigned b1) {
    asm volatile(
        "mma.sync.aligned.m16n8k16.row.col.f32.bf16.bf16.f32 "
        "{%0,%1,%2,%3}, {%4,%5,%6,%7}, {%8,%9}, {%0,%1,%2,%3};"
        : "+f"(d[0]), "+f"(d[1]), "+f"(d[2]), "+f"(d[3])
        : "r"(a0), "r"(a1), "r"(a2), "r"(a3), "r"(b0), "r"(b1));
}

// ---------------------------------------------------------------------------
// Kernel 0: prep — split W_node into mma B fragments; fold exp(b_edge) into
//           node LN affine params.
// ---------------------------------------------------------------------------
__global__ __launch_bounds__(256) void prep_kernel(
    const float* __restrict__ Wn, const float* __restrict__ gn,
    const float* __restrict__ bn, const float* __restrict__ be)
{
    const int i = blockIdx.x * 256 + threadIdx.x;   // 0..8191
    const int lane = i & 31, n = (i >> 5) & 15, ks = i >> 9;
    const int k0 = 16 * ks + 2 * (lane & 3);
    const int c  = 8 * n + (lane >> 2);
    const float v00 = Wn[(k0+0)*HID + c], v01 = Wn[(k0+1)*HID + c];
    const float v10 = Wn[(k0+8)*HID + c], v11 = Wn[(k0+9)*HID + c];
    unsigned h0, l0, h1, l1;
    split2(make_float2(v00, v01), h0, l0);
    split2(make_float2(v10, v11), h1, l1);
    g_WnF[i] = make_uint4(h0, h1, l0, l1);
    if (i < HID) {
        const float e = __expf(be[i]);
        g_P[i] = gn[i] * e;
        g_Q[i] = bn[i] * e;
    }
}

// ---------------------------------------------------------------------------
// Kernel 1: hv = (LN(GELU(nf @ Wn)) scaled by exp(b_edge)), MMA split-3.
// Full W_node fragment table (128 KB) in dynamic smem; 12 warps/SM,
// warps grid-stride over 16-node tiles. Also zeroes each tile's g_h rows.
// ---------------------------------------------------------------------------
__global__ __launch_bounds__(384) void node_proj_kernel(const float* __restrict__ nf)
{
    extern __shared__ uint4 sBn[];   // 16*16*32 = 8192 uint4 = 128 KB

    const int tid = threadIdx.x;
    for (int i = tid; i < 8192; i += 384) sBn[i] = g_WnF[i];
    __syncthreads();

    const int w = tid >> 5, lane = tid & 31;
    const int gid = lane >> 2, tig = lane & 3;
    const int nwarp = gridDim.x * 12;
    const float2* nf2 = (const float2*)nf;

    for (int t = blockIdx.x * 12 + w; t < N_NODES / 16; t += nwarp) {
        const int n0 = t * 16;

        // zero accumulator rows n0..n0+15 (8 KB per warp)
        {
            float4* hz = (float4*)(g_h + (size_t)n0 * HID);
            const float4 z4 = make_float4(0.f, 0.f, 0.f, 0.f);
            #pragma unroll
            for (int i = 0; i < 16; i++) hz[i * 32 + lane] = z4;
        }

        float d[16][4];
        #pragma unroll
        for (int n = 0; n < 16; n++) { d[n][0]=0.f; d[n][1]=0.f; d[n][2]=0.f; d[n][3]=0.f; }

        const size_t r0 = (size_t)(n0 + gid) * (NODE_IN/2);
        const size_t r1 = (size_t)(n0 + gid + 8) * (NODE_IN/2);
        #pragma unroll 4
        for (int ks = 0; ks < 16; ks++) {
            const float2 f0 = nf2[r0 + 8*ks + tig    ];
            const float2 f1 = nf2[r1 + 8*ks + tig    ];
            const float2 f2 = nf2[r0 + 8*ks + tig + 4];
            const float2 f3 = nf2[r1 + 8*ks + tig + 4];
            unsigned ah0, al0, ah1, al1, ah2, al2, ah3, al3;
            split2(f0, ah0, al0); split2(f1, ah1, al1);
            split2(f2, ah2, al2); split2(f3, ah3, al3);

            const uint4* Bk = &sBn[ks * 512 + lane];
            #pragma unroll
            for (int n = 0; n < 16; n++) {
                const uint4 bb = Bk[n * 32];
                mma_bf16(d[n], ah0, ah1, ah2, ah3, bb.x, bb.y);
                mma_bf16(d[n], ah0, ah1, ah2, ah3, bb.z, bb.w);
                mma_bf16(d[n], al0, al1, al2, al3, bb.x, bb.y);
            }
        }

        // GELU
        #pragma unroll
        for (int n = 0; n < 16; n++) {
            d[n][0] = gelu_exact(d[n][0]); d[n][1] = gelu_exact(d[n][1]);
            d[n][2] = gelu_exact(d[n][2]); d[n][3] = gelu_exact(d[n][3]);
        }

        // LN stats per node row (quad reduce)
        float s0 = 0.f, q0 = 0.f, s1 = 0.f, q1 = 0.f;
        #pragma unroll
        for (int n = 0; n < 16; n++) {
            s0 += d[n][0] + d[n][1];
            q0 += d[n][0]*d[n][0] + d[n][1]*d[n][1];
            s1 += d[n][2] + d[n][3];
            q1 += d[n][2]*d[n][2] + d[n][3]*d[n][3];
        }
        s0 += __shfl_xor_sync(0xffffffffu, s0, 1); s0 += __shfl_xor_sync(0xffffffffu, s0, 2);
        q0 += __shfl_xor_sync(0xffffffffu, q0, 1); q0 += __shfl_xor_sync(0xffffffffu, q0, 2);
        s1 += __shfl_xor_sync(0xffffffffu, s1, 1); s1 += __shfl_xor_sync(0xffffffffu, s1, 2);
        q1 += __shfl_xor_sync(0xffffffffu, q1, 1); q1 += __shfl_xor_sync(0xffffffffu, q1, 2);
        const float mu0   = s0 * (1.f / HID);
        const float rstd0 = rsqrtf(q0 * (1.f / HID) - mu0*mu0 + EPS);
        const float mu1   = s1 * (1.f / HID);
        const float rstd1 = rsqrtf(q1 * (1.f / HID) - mu1*mu1 + EPS);

        float* o0 = g_hv + (size_t)(n0 + gid    ) * HID;
        float* o1 = g_hv + (size_t)(n0 + gid + 8) * HID;
        #pragma unroll
        for (int n = 0; n < 16; n++) {
            const int c0 = 8*n + 2*tig;
            const float2 P2 = *(const float2*)(g_P + c0);
            const float2 Q2 = *(const float2*)(g_Q + c0);
            *(float2*)(o0 + c0) = make_float2(
                (d[n][0]-mu0)*rstd0*P2.x + Q2.x, (d[n][1]-mu0)*rstd0*P2.y + Q2.y);
            *(float2*)(o1 + c0) = make_float2(
                (d[n][2]-mu1)*rstd1*P2.x + Q2.x, (d[n][3]-mu1)*rstd1*P2.y + Q2.y);
        }
    }
}

// ---------------------------------------------------------------------------
// Kernel 2 (hot): per 16-edge warp tile:
//   z = ef @ W_edge via mma.sync bf16 3-term split (~fp32 accuracy)
//   he = exp(LN(z)*g)  (b folded into hv);  red.v4(h[dst], hv[src]*he)
// Scatter: lanes tig/tig^1 pair up via shfl so even-tig lanes issue
// 16B red.global.add.v4 (halves REDG lane-requests vs v2).
// ---------------------------------------------------------------------------
__global__ __launch_bounds__(128, 4) void edge_kernel(
    const float* __restrict__ ef, const int* __restrict__ src,
    const int* __restrict__ dst,  const float* __restrict__ We,
    const float* __restrict__ g)
{
    // Pre-split B fragments: [ks][n][lane] -> {bhi0, bhi1, blo0, blo1}
    __shared__ uint4 sB[4 * 16 * 32];   // 32 KB

    const int tid = threadIdx.x;
    for (int i = tid; i < 2048; i += 128) {
        const int lane = i & 31, n = (i >> 5) & 15, ks = i >> 9;
        const int k0 = 16*ks + 2*(lane & 3);
        const int c  = 8*n + (lane >> 2);
        const float v00 = We[(k0+0)*HID + c], v01 = We[(k0+1)*HID + c];
        const float v10 = We[(k0+8)*HID + c], v11 = We[(k0+9)*HID + c];
        unsigned h0, l0, h1, l1;
        split2(make_float2(v00, v01), h0, l0);
        split2(make_float2(v10, v11), h1, l1);
        sB[i] = make_uint4(h0, h1, l0, l1);
    }
    __syncthreads();

    const int w = tid >> 5, lane = tid & 31;
    const int gid = lane >> 2, tig = lane & 3;
    const bool evenTig = (tig & 1) == 0;

    const float2* ef2 = (const float2*)ef;
    const int nTiles = N_EDGES / 16;      // 50000, exact
    const int nwarp  = gridDim.x * 4;

    for (int t = blockIdx.x * 4 + w; t < nTiles; t += nwarp) {
        const int e0 = t * 16;

        // prefetch indices before the MMA loop (hide L2 latency)
        const int er0 = e0 + gid, er1 = e0 + gid + 8;
        const int sv0 = __ldg(&src[er0]), dv0 = __ldg(&dst[er0]);
        const int sv1 = __ldg(&src[er1]), dv1 = __ldg(&dst[er1]);

        float d[16][4];
        #pragma unroll
        for (int n = 0; n < 16; n++) { d[n][0]=0.f; d[n][1]=0.f; d[n][2]=0.f; d[n][3]=0.f; }

        #pragma unroll
        for (int ks = 0; ks < 4; ks++) {
            const float2 f0 = ef2[(size_t)(e0 + gid    ) * 32 + 8*ks + tig    ];
            const float2 f1 = ef2[(size_t)(e0 + gid + 8) * 32 + 8*ks + tig    ];
            const float2 f2 = ef2[(size_t)(e0 + gid    ) * 32 + 8*ks + tig + 4];
            const float2 f3 = ef2[(size_t)(e0 + gid + 8) * 32 + 8*ks + tig + 4];
            unsigned ah0, al0, ah1, al1, ah2, al2, ah3, al3;
            split2(f0, ah0, al0); split2(f1, ah1, al1);
            split2(f2, ah2, al2); split2(f3, ah3, al3);

            const uint4* sBk = &sB[ks * 512 + lane];
            #pragma unroll
            for (int n = 0; n < 16; n++) {
                const uint4 bb = sBk[n * 32];
                mma_bf16(d[n], ah0, ah1, ah2, ah3, bb.x, bb.y);  // hi*hi
                mma_bf16(d[n], ah0, ah1, ah2, ah3, bb.z, bb.w);  // hi*lo
                mma_bf16(d[n], al0, al1, al2, al3, bb.x, bb.y);  // lo*hi
            }
        }

        // LN stats per edge row (quad-reduce: lanes sharing gid)
        float s0 = 0.f, q0 = 0.f, s1 = 0.f, q1 = 0.f;
        #pragma unroll
        for (int n = 0; n < 16; n++) {
            s0 += d[n][0] + d[n][1];
            q0 += d[n][0]*d[n][0] + d[n][1]*d[n][1];
            s1 += d[n][2] + d[n][3];
            q1 += d[n][2]*d[n][2] + d[n][3]*d[n][3];
        }
        s0 += __shfl_xor_sync(0xffffffffu, s0, 1); s0 += __shfl_xor_sync(0xffffffffu, s0, 2);
        q0 += __shfl_xor_sync(0xffffffffu, q0, 1); q0 += __shfl_xor_sync(0xffffffffu, q0, 2);
        s1 += __shfl_xor_sync(0xffffffffu, s1, 1); s1 += __shfl_xor_sync(0xffffffffu, s1, 2);
        q1 += __shfl_xor_sync(0xffffffffu, q1, 1); q1 += __shfl_xor_sync(0xffffffffu, q1, 2);

        const float mu0   = s0 * (1.f / HID);
        const float rstd0 = rsqrtf(q0 * (1.f / HID) - mu0*mu0 + EPS);
        const float mu1   = s1 * (1.f / HID);
        const float rstd1 = rsqrtf(q1 * (1.f / HID) - mu1*mu1 + EPS);

        const float2* hv0 = (const float2*)g_hv + (size_t)sv0 * 64 + tig;
        const float2* hv1 = (const float2*)g_hv + (size_t)sv1 * 64 + tig;
        float* o0 = g_h + (size_t)dv0 * HID + 2*tig;
        float* o1 = g_h + (size_t)dv1 * HID + 2*tig;

        #pragma unroll
        for (int n = 0; n < 16; n++) {
            const float2 ge = __ldg((const float2*)(g + 8*n + 2*tig));
            const float e00 = __expf((d[n][0] - mu0) * rstd0 * ge.x);
            const float e01 = __expf((d[n][1] - mu0) * rstd0 * ge.y);
            const float e10 = __expf((d[n][2] - mu1) * rstd1 * ge.x);
            const float e11 = __expf((d[n][3] - mu1) * rstd1 * ge.y);
            const float2 h0 = hv0[4*n];
            const float2 h1 = hv1[4*n];
            const float m00 = h0.x * e00, m01 = h0.y * e01;
            const float m10 = h1.x * e10, m11 = h1.y * e11;
            // pair lanes tig/tig^1 -> even-tig lane issues 16B red.v4
            const float p00 = __shfl_xor_sync(0xffffffffu, m00, 1);
            const float p01 = __shfl_xor_sync(0xffffffffu, m01, 1);
            const float p10 = __shfl_xor_sync(0xffffffffu, m10, 1);
            const float p11 = __shfl_xor_sync(0xffffffffu, m11, 1);
            if (evenTig) {
                red_add_v4(o0 + 8*n, m00, m01, p00, p01);
                red_add_v4(o1 + 8*n, m10, m11, p10, p11);
            }
        }
    }
}

// ---------------------------------------------------------------------------
// Kernel 3: out = LayerNorm(GELU(h @ W_out))
// ---------------------------------------------------------------------------
__global__ __launch_bounds__(256) void out_kernel(
    const float* __restrict__ Wo, const float* __restrict__ g,
    const float* __restrict__ b,  float* __restrict__ out)
{
    __shared__ float sH [16 * HID];        // 8 KB
    __shared__ float sWo[HID * OUT_DIM];   // 8 KB

    const int tid = threadIdx.x;
    const int n0  = blockIdx.x * 16;
    {
        const float4* hv4 = (const float4*)(g_h + (size_t)n0 * HID);
        float4* sH4 = (float4*)sH;
        #pragma unroll
        for (int i = tid; i < 512; i += 256) sH4[i] = hv4[i];
        const float4* wv4 = (const float4*)Wo;
        float4* sW4 = (float4*)sWo;
        #pragma unroll
        for (int i = tid; i < 512; i += 256) sW4[i] = wv4[i];
    }
    __syncthreads();

    const int n = tid >> 4, c = tid & 15;
    float acc = 0.f;
    const float4* sHn = (const float4*)(sH + n * HID);
    #pragma unroll 4
    for (int k4 = 0; k4 < HID / 4; k4++) {
        const float4 a = sHn[k4];
        acc += a.x * sWo[(4*k4+0)*OUT_DIM + c];
        acc += a.y * sWo[(4*k4+1)*OUT_DIM + c];
        acc += a.z * sWo[(4*k4+2)*OUT_DIM + c];
        acc += a.w * sWo[(4*k4+3)*OUT_DIM + c];
    }

    const float v = gelu_exact(acc);
    float s = v, s2 = v * v;
    #pragma unroll
    for (int off = 8; off; off >>= 1) {
        s  += __shfl_xor_sync(0xffffffffu, s,  off);
        s2 += __shfl_xor_sync(0xffffffffu, s2, off);
    }
    const float mu   = s * (1.f / OUT_DIM);
    const float rstd = rsqrtf(s2 * (1.f / OUT_DIM) - mu * mu + EPS);
    out[(size_t)(n0 + n) * OUT_DIM + c] = (v - mu) * rstd * g[c] + b[c];
}

// ---------------------------------------------------------------------------
extern "C" void kernel_launch(void* const* d_in, const int* in_sizes, int n_in,
                              void* d_out, int out_size) {
    const float* node_feats = (const float*)d_in[0];
    const float* edge_feats = (const float*)d_in[1];
    const int*   src        = (const int*)  d_in[2];
    const int*   dst        = (const int*)  d_in[3];
    const float* W_node     = (const float*)d_in[4];
    const float* g_node     = (const float*)d_in[5];
    const float* b_node     = (const float*)d_in[6];
    const float* W_edge     = (const float*)d_in[7];
    const float* g_edge     = (const float*)d_in[8];
    const float* b_edge     = (const float*)d_in[9];
    const float* W_out      = (const float*)d_in[10];
    const float* g_out      = (const float*)d_in[11];
    const float* b_out      = (const float*)d_in[12];
    float* out = (float*)d_out;

    static bool attr_set = false;
    if (!attr_set) {
        cudaFuncSetAttribute(node_proj_kernel,
                             cudaFuncAttributeMaxDynamicSharedMemorySize, 131072);
        attr_set = true;
    }

    prep_kernel<<<32, 256>>>(W_node, g_node, b_node, b_edge);
    node_proj_kernel<<<148, 384, 131072>>>(node_feats);
    edge_kernel<<<592, 128>>>(edge_feats, src, dst, W_edge, g_edge);
    out_kernel<<<N_NODES / 16, 256>>>(W_out, g_out, b_out, out);
}